// round 14
// baseline (speedup 1.0000x reference)
#include <cuda_runtime.h>
#include <cuda_bf16.h>
#include <math.h>
#include <stdint.h>

// ---------------- problem constants ----------------
#define BB   2
#define TT   2048
#define HIDD 1024
#define HH   16
#define MT   (BB*TT)          // 4096 rows
#define KSCALE 0.125f
#define LNEPS 1e-5f
#define GK   1024             // GEMM K
#define NCHUNK 16             // 1024/64

// ---------------- scratch (device globals) ----------------
__device__ float g_zq[MT*HIDD];
__device__ float g_zk[MT*HIDD];
__device__ float g_zv[MT*HIDD];
__device__ float g_za[MT*HIDD];
__device__ float g_zg[MT*HIDD];
__device__ float g_zb[MT*HH];
__device__ float g_q [MT*HIDD];
__device__ float g_k [MT*HIDD];
__device__ float g_v [MT*HIDD];
__device__ float g_o [MT*HIDD];

__device__ __nv_bfloat16 g_xhi[MT*HIDD];
__device__ __nv_bfloat16 g_xlo[MT*HIDD];
__device__ __nv_bfloat16 g_whi[6*HIDD*HIDD];
__device__ __nv_bfloat16 g_wlo[6*HIDD*HIDD];
__device__ __nv_bfloat16 g_oghi[MT*HIDD];
__device__ __nv_bfloat16 g_oglo[MT*HIDD];

__device__ __forceinline__ float sigmoidf_(float x) {
    return 1.0f / (1.0f + __expf(-x));
}

// ---------------- cp.async helpers ----------------
__device__ __forceinline__ void cp_async16_s(uint32_t dst, const void* src) {
    asm volatile("cp.async.cg.shared.global [%0], [%1], 16;\n" :: "r"(dst), "l"(src));
}
__device__ __forceinline__ void cp_async16(void* dst, const void* src) {
    unsigned d = (unsigned)__cvta_generic_to_shared(dst);
    asm volatile("cp.async.ca.shared.global [%0], [%1], 16;\n" :: "r"(d), "l"(src));
}
__device__ __forceinline__ void cp_async4(void* dst, const void* src) {
    unsigned d = (unsigned)__cvta_generic_to_shared(dst);
    asm volatile("cp.async.ca.shared.global [%0], [%1], 4;\n" :: "r"(d), "l"(src));
}
__device__ __forceinline__ void cp_commit() { asm volatile("cp.async.commit_group;\n"); }
__device__ __forceinline__ void cp_wait2()  { asm volatile("cp.async.wait_group 2;\n"); }
__device__ __forceinline__ void cp_wait1()  { asm volatile("cp.async.wait_group 1;\n"); }
__device__ __forceinline__ void cp_wait0()  { asm volatile("cp.async.wait_group 0;\n"); }

// ---------------- mma.sync / ldmatrix ----------------
__device__ __forceinline__ void ldsm4(uint32_t* r, uint32_t addr) {
    asm volatile("ldmatrix.sync.aligned.m8n8.x4.shared.b16 {%0,%1,%2,%3}, [%4];"
        : "=r"(r[0]), "=r"(r[1]), "=r"(r[2]), "=r"(r[3]) : "r"(addr));
}
__device__ __forceinline__ void mma16816(float* c, const uint32_t* a, const uint32_t* b) {
    asm volatile("mma.sync.aligned.m16n8k16.row.col.f32.bf16.bf16.f32 "
        "{%0,%1,%2,%3}, {%4,%5,%6,%7}, {%8,%9}, {%0,%1,%2,%3};"
        : "+f"(c[0]), "+f"(c[1]), "+f"(c[2]), "+f"(c[3])
        : "r"(a[0]), "r"(a[1]), "r"(a[2]), "r"(a[3]), "r"(b[0]), "r"(b[1]));
}

// =====================================================================
// prep_all: 6 weight splits (y<6), 2 x-split halves (y=6,7), beta GEMV (y=8)
// =====================================================================
__device__ __forceinline__ void split4(const float* __restrict__ in,
    __nv_bfloat16* __restrict__ hi, __nv_bfloat16* __restrict__ lo, int base)
{
    float4 xv[4];
    #pragma unroll
    for (int j = 0; j < 4; j++)
        xv[j] = ((const float4*)in)[base + j * 256];
    #pragma unroll
    for (int j = 0; j < 4; j++) {
        int i = base + j * 256;
        float xs[4] = {xv[j].x, xv[j].y, xv[j].z, xv[j].w};
        __align__(8) __nv_bfloat16 h[4];
        __align__(8) __nv_bfloat16 l[4];
        #pragma unroll
        for (int q = 0; q < 4; q++) {
            h[q] = __float2bfloat16(xs[q]);
            l[q] = __float2bfloat16(xs[q] - __bfloat162float(h[q]));
        }
        *(uint2*)(hi + (size_t)i * 4) = *(uint2*)h;
        *(uint2*)(lo + (size_t)i * 4) = *(uint2*)l;
    }
}

__global__ __launch_bounds__(256) void prep_all(
    const float* x,
    const float* w0, const float* w1, const float* w2,
    const float* w3, const float* w4, const float* w5,
    __nv_bfloat16* __restrict__ whi, __nv_bfloat16* __restrict__ wlo,
    __nv_bfloat16* __restrict__ xhi, __nv_bfloat16* __restrict__ xlo,
    const float* __restrict__ Wb, const float* __restrict__ bb,
    float* __restrict__ zb)
{
    const int y = blockIdx.y;
    const int tid = threadIdx.x;
    if (y < 6) {
        if (blockIdx.x >= 256) return;
        const float* in = (y == 0) ? w0 : (y == 1) ? w1 : (y == 2) ? w2
                        : (y == 3) ? w3 : (y == 4) ? w4 : w5;
        const size_t W = (size_t)HIDD * HIDD;
        split4(in, whi + y * W, wlo + y * W, blockIdx.x * 1024 + tid);
    } else if (y < 8) {
        const int half = y - 6;
        const int X4h = MT * HIDD / 8;
        int base = blockIdx.x * 1024 + tid;
        split4(x + (size_t)half * X4h * 4,
               xhi + (size_t)half * X4h * 4, xlo + (size_t)half * X4h * 4, base);
    } else {
        const int w    = tid >> 5;
        const int lane = tid & 31;
        const int n    = lane >> 1;
        const int kseg = lane & 1;
        const int m    = blockIdx.x * 8 + w;
        const float4* xr = (const float4*)(x  + (size_t)m * HIDD + kseg * 512);
        const float4* wr = (const float4*)(Wb + (size_t)n * HIDD + kseg * 512);
        float a0 = 0.f, a1 = 0.f, a2 = 0.f, a3 = 0.f;
        #pragma unroll 8
        for (int i = 0; i < 128; i += 4) {
            float4 x0 = xr[i+0], q0 = wr[i+0];
            float4 x1 = xr[i+1], q1 = wr[i+1];
            float4 x2 = xr[i+2], q2 = wr[i+2];
            float4 x3 = xr[i+3], q3 = wr[i+3];
            a0 = fmaf(x0.x, q0.x, a0); a0 = fmaf(x0.y, q0.y, a0);
            a0 = fmaf(x0.z, q0.z, a0); a0 = fmaf(x0.w, q0.w, a0);
            a1 = fmaf(x1.x, q1.x, a1); a1 = fmaf(x1.y, q1.y, a1);
            a1 = fmaf(x1.z, q1.z, a1); a1 = fmaf(x1.w, q1.w, a1);
            a2 = fmaf(x2.x, q2.x, a2); a2 = fmaf(x2.y, q2.y, a2);
            a2 = fmaf(x2.z, q2.z, a2); a2 = fmaf(x2.w, q2.w, a2);
            a3 = fmaf(x3.x, q3.x, a3); a3 = fmaf(x3.y, q3.y, a3);
            a3 = fmaf(x3.z, q3.z, a3); a3 = fmaf(x3.w, q3.w, a3);
        }
        float acc = (a0 + a1) + (a2 + a3);
        acc += __shfl_xor_sync(0xffffffffu, acc, 1);
        if (kseg == 0)
            zb[(size_t)m * HH + n] = sigmoidf_(acc + bb[n]);
    }
}

// =====================================================================
// bf16x3 GEMM 128x128 tile, K-chunk 64, SW128, 3-stage cp.async pipeline.
// 512 threads = 16 warps (4 M x 4 N), warp tile 32x32.  (R8 config)
// =====================================================================
#define TILEB  16384u
#define STAGEB (4u*TILEB)
#define NSTAGE 3
#define GTHR   512

__device__ __forceinline__ void gemm_core_w(
    const __nv_bfloat16* __restrict__ baseAh, const __nv_bfloat16* __restrict__ baseAl,
    const __nv_bfloat16* __restrict__ baseBh, const __nv_bfloat16* __restrict__ baseBl,
    const float* __restrict__ bias, float* __restrict__ Cbase, int mode)
{
    extern __shared__ char dyns[];
    uint32_t sb0 = (uint32_t)__cvta_generic_to_shared(dyns);
    const uint32_t tiles = (sb0 + 1023) & ~1023u;

    const int tid  = threadIdx.x;
    const int wid  = tid >> 5;
    const int lane = tid & 31;
    const int mbase = (wid >> 2) * 32;
    const int nbase = (wid & 3) * 32;

    const uint32_t sx  = (uint32_t)((lane & 7) << 4);
    const uint32_t khA = (lane & 16) ? 16u : 0u;
    const uint32_t khB = (lane & 8)  ? 16u : 0u;
    uint32_t rowA[2], rowB[2];
    #pragma unroll
    for (int mf = 0; mf < 2; mf++)
        rowA[mf] = (uint32_t)((mbase + mf * 16 + (lane & 15)) * 128);
    #pragma unroll
    for (int nf2 = 0; nf2 < 2; nf2++)
        rowB[nf2] = (uint32_t)((nbase + nf2 * 16 + (lane & 7) + ((lane & 16) ? 8 : 0)) * 128);

    float acc[2][4][4];
    #pragma unroll
    for (int mf = 0; mf < 2; mf++)
        #pragma unroll
        for (int nf = 0; nf < 4; nf++)
            #pragma unroll
            for (int j = 0; j < 4; j++) acc[mf][nf][j] = 0.0f;

    auto issue = [&](int kc, int st) {
        uint32_t tb = tiles + (uint32_t)st * STAGEB;
        #pragma unroll
        for (int it = 0; it < 2; it++) {
            int v = tid + it * GTHR;
            int row = v >> 3, c8 = v & 7;
            uint32_t off = (uint32_t)(row * 128 + c8 * 16);
            uint32_t sw  = off ^ ((off >> 3) & 0x70);
            size_t goff = (size_t)row * GK + (size_t)kc * 64 + c8 * 8;
            cp_async16_s(tb + sw,             baseAh + goff);
            cp_async16_s(tb + TILEB + sw,     baseAl + goff);
            cp_async16_s(tb + 2u*TILEB + sw,  baseBh + goff);
            cp_async16_s(tb + 3u*TILEB + sw,  baseBl + goff);
        }
    };

    issue(0, 0); cp_commit();
    issue(1, 1); cp_commit();
    issue(2, 2); cp_commit();

    for (int c = 0; c < NCHUNK; c++) {
        if (c <= NCHUNK - 3)      cp_wait2();
        else if (c == NCHUNK - 2) cp_wait1();
        else                      cp_wait0();
        __syncthreads();

        const int st = c % NSTAGE;
        const uint32_t tbAh = tiles + (uint32_t)st * STAGEB;
        const uint32_t tbAl = tbAh + TILEB;
        const uint32_t tbBh = tbAl + TILEB;
        const uint32_t tbBl = tbBh + TILEB;

        #pragma unroll
        for (int s = 0; s < 4; s++) {
            const uint32_t kxA = ((uint32_t)(s * 32) + khA) ^ sx;
            const uint32_t kxB = ((uint32_t)(s * 32) + khB) ^ sx;

            uint32_t ah[2][4], al[2][4], bh[4][2], bl[4][2];
            #pragma unroll
            for (int mf = 0; mf < 2; mf++) {
                ldsm4(ah[mf], tbAh + rowA[mf] + kxA);
                ldsm4(al[mf], tbAl + rowA[mf] + kxA);
            }
            #pragma unroll
            for (int nf2 = 0; nf2 < 2; nf2++) {
                uint32_t t[4];
                ldsm4(t, tbBh + rowB[nf2] + kxB);
                bh[nf2*2][0] = t[0]; bh[nf2*2][1] = t[1];
                bh[nf2*2+1][0] = t[2]; bh[nf2*2+1][1] = t[3];
                ldsm4(t, tbBl + rowB[nf2] + kxB);
                bl[nf2*2][0] = t[0]; bl[nf2*2][1] = t[1];
                bl[nf2*2+1][0] = t[2]; bl[nf2*2+1][1] = t[3];
            }
            #pragma unroll
            for (int mf = 0; mf < 2; mf++)
                #pragma unroll
                for (int nf = 0; nf < 4; nf++) {
                    mma16816(acc[mf][nf], ah[mf], bh[nf]);
                    mma16816(acc[mf][nf], ah[mf], bl[nf]);
                    mma16816(acc[mf][nf], al[mf], bh[nf]);
                }
        }
        __syncthreads();

        if (c + NSTAGE < NCHUNK) {
            issue(c + NSTAGE, st);
            cp_commit();
        }
    }

    const int rq = lane >> 2;
    const int cq = (lane & 3) * 2;
    #pragma unroll
    for (int mf = 0; mf < 2; mf++) {
        #pragma unroll
        for (int nf = 0; nf < 4; nf++) {
            int m0  = mbase + mf * 16 + rq;
            int col = nbase + nf * 8 + cq;
            float r0 = acc[mf][nf][0], r1 = acc[mf][nf][1];
            float r2 = acc[mf][nf][2], r3 = acc[mf][nf][3];
            if (mode == 1) {
                float b0 = bias[col], b1 = bias[col + 1];
                r0 = sigmoidf_(r0 + b0); r1 = sigmoidf_(r1 + b1);
                r2 = sigmoidf_(r2 + b0); r3 = sigmoidf_(r3 + b1);
            } else if (mode == 2) {
                r0 = sigmoidf_(r0); r1 = sigmoidf_(r1);
                r2 = sigmoidf_(r2); r3 = sigmoidf_(r3);
            }
            *(float2*)&Cbase[(size_t)m0 * HIDD + col]       = make_float2(r0, r1);
            *(float2*)&Cbase[(size_t)(m0 + 8) * HIDD + col] = make_float2(r2, r3);
        }
    }
}

__global__ __launch_bounds__(GTHR, 1) void gemm_mma5(
    const __nv_bfloat16* __restrict__ xhi, const __nv_bfloat16* __restrict__ xlo,
    const __nv_bfloat16* __restrict__ whi, const __nv_bfloat16* __restrict__ wlo,
    float* z0, float* z1, float* z2, float* z3, float* z4,
    const float* __restrict__ ba)
{
    const int slot = blockIdx.x >> 3;
    const int bnw  = (blockIdx.x & 7) * 128;
    const int bm   = blockIdx.y * 128;
    const size_t W = (size_t)HIDD * HIDD;
    float* C = (slot == 0) ? z0 : (slot == 1) ? z1 : (slot == 2) ? z2
             : (slot == 3) ? z3 : z4;
    const int mode = (slot == 3) ? 1 : (slot == 4) ? 2 : 0;
    gemm_core_w(xhi + (size_t)bm * GK, xlo + (size_t)bm * GK,
                whi + slot * W + (size_t)bnw * GK, wlo + slot * W + (size_t)bnw * GK,
                (slot == 3) ? (ba + bnw) : nullptr,
                C + (size_t)bm * HIDD + bnw, mode);
}

__global__ __launch_bounds__(GTHR, 1) void gemm_mma1(
    const __nv_bfloat16* __restrict__ Ahi, const __nv_bfloat16* __restrict__ Alo,
    const __nv_bfloat16* __restrict__ Bhi, const __nv_bfloat16* __restrict__ Blo,
    float* __restrict__ C)
{
    const int bn = blockIdx.x * 128;
    const int bm = blockIdx.y * 128;
    gemm_core_w(Ahi + (size_t)bm * GK, Alo + (size_t)bm * GK,
                Bhi + (size_t)bn * GK, Blo + (size_t)bn * GK,
                nullptr, C + (size_t)bm * HIDD + bn, 0);
}

// =====================================================================
// fused causal depthwise conv (K=4) + SiLU for q/k/v; grid.y selects branch
// =====================================================================
__global__ __launch_bounds__(256) void conv3(
    const float* __restrict__ zq, const float* __restrict__ zk, const float* __restrict__ zv,
    const float* __restrict__ qcw, const float* __restrict__ qcb,
    const float* __restrict__ kcw, const float* __restrict__ kcb,
    const float* __restrict__ vcw, const float* __restrict__ vcb,
    float* __restrict__ oq, float* __restrict__ ok, float* __restrict__ ov)
{
    const int br = blockIdx.y;
    const float* z    = (br == 0) ? zq  : (br == 1) ? zk  : zv;
    const float* w    = (br == 0) ? qcw : (br == 1) ? kcw : vcw;
    const float* bias = (br == 0) ? qcb : (br == 1) ? kcb : vcb;
    float* out        = (br == 0) ? oq  : (br == 1) ? ok  : ov;
    const float scale = (br == 1) ? KSCALE : 1.0f;

    int idx = blockIdx.x * blockDim.x + threadIdx.x;
    int bt = idx >> 8;
    int c0 = (idx & 255) * 4;
    int b  = bt >> 11;
    int t  = bt & 2047;

    float wl[16];
    *(float4*)(wl)      = *(const float4*)&w[c0*4];
    *(float4*)(wl + 4)  = *(const float4*)&w[c0*4 + 4];
    *(float4*)(wl + 8)  = *(const float4*)&w[c0*4 + 8];
    *(float4*)(wl + 12) = *(const float4*)&w[c0*4 + 12];

    float av[4];
    *(float4*)av = *(const float4*)&bias[c0];

    #pragma unroll
    for (int j = 0; j < 4; j++) {
        int tt = t - 3 + j;
        if (tt < 0) continue;
        float zl[4];
        *(float4*)zl = *(const float4*)&z[((size_t)(b*TT + tt)) * HIDD + c0];
        #pragma unroll
        for (int cc = 0; cc < 4; cc++)
            av[cc] = fmaf(wl[cc*4 + j], zl[cc], av[cc]);
    }
    float4 o4;
    float* op = &o4.x;
    #pragma unroll
    for (int cc = 0; cc < 4; cc++) {
        float xv = av[cc];
        op[cc] = scale * xv * sigmoidf_(xv);
    }
    *(float4*)&out[(size_t)bt * HIDD + c0] = o4;
}

// =====================================================================
// Sequential scan (R11 algorithm) + register prefetch of next step's
// k/q/a/b/v so LDS latency is off the critical chain.
// grid (4,H,B) x 128 thr (16 rows x 8 lanes). TCH=16 double-buffered.
// =====================================================================
#define TCH 16
__global__ __launch_bounds__(128, 1) void scan_kernel(
    const float* __restrict__ q, const float* __restrict__ k,
    const float* __restrict__ v, const float* __restrict__ za,
    const float* __restrict__ zb, float* __restrict__ o)
{
    const int rc  = blockIdx.x;
    const int h   = blockIdx.y;
    const int b   = blockIdx.z;
    const int tid = threadIdx.x;
    const int r   = tid >> 3;
    const int cg  = tid & 7;
    const int i   = rc * 16 + r;

    __shared__ __align__(16) float kb[2][TCH][64];
    __shared__ __align__(16) float qb[2][TCH][64];
    __shared__ __align__(16) float vb[2][TCH][16];
    __shared__ __align__(16) float ab[2][TCH][16];
    __shared__ __align__(16) float bbuf[2][TCH];

    float S[8];
    #pragma unroll
    for (int j = 0; j < 8; j++) S[j] = 0.0f;

    const size_t base = ((size_t)b * TT) * HH + h;

    auto issue = [&](int c, int buf) {
        int t0 = c * TCH;
        #pragma unroll
        for (int it = 0; it < 2; it++) {
            int idx = tid + it * 128;
            int tt = idx >> 4, f = idx & 15;
            size_t off = (base + (size_t)(t0 + tt) * HH) * 64 + f * 4;
            cp_async16(&kb[buf][tt][f*4], k + off);
            cp_async16(&qb[buf][tt][f*4], q + off);
        }
        if (tid < 64) {
            int tt = tid >> 2, f = tid & 3;
            size_t off = (base + (size_t)(t0 + tt) * HH) * 64 + rc*16 + f*4;
            cp_async16(&vb[buf][tt][f*4], v + off);
        } else {
            int t2 = tid - 64;
            int tt = t2 >> 2, f = t2 & 3;
            size_t off = (base + (size_t)(t0 + tt) * HH) * 64 + rc*16 + f*4;
            cp_async16(&ab[buf][tt][f*4], za + off);
        }
        if (tid < TCH)
            cp_async4(&bbuf[buf][tid], zb + ((size_t)(b*TT + t0 + tid)) * HH + h);
    };

    const int NCH = TT / TCH;
    issue(0, 0);
    cp_commit();

    for (int c = 0; c < NCH; c++) {
        const int buf = c & 1;
        if (c + 1 < NCH) {
            issue(c + 1, buf ^ 1);
            cp_commit();
            cp_wait1();
        } else {
            cp_wait0();
        }
        __syncthreads();

        // prime step 0 registers
        float kk[8], qq[8];
        *(float4*)(kk)     = *(const float4*)&kb[buf][0][cg*8];
        *(float4*)(kk + 4) = *(const float4*)&kb[buf][0][cg*8 + 4];
        *(float4*)(qq)     = *(const float4*)&qb[buf][0][cg*8];
        *(float4*)(qq + 4) = *(const float4*)&qb[buf][0][cg*8 + 4];
        float av  = ab[buf][0][r];
        float bv  = bbuf[buf][0];
        float bvv = bv * vb[buf][0][r];

        #pragma unroll
        for (int tt = 0; tt < TCH; tt++) {
            // prefetch next step's operands (consumed ~1 chain-length later)
            float nk[8], nq[8], nav = 0.f, nbv = 0.f, nbvv = 0.f;
            if (tt + 1 < TCH) {
                *(float4*)(nk)     = *(const float4*)&kb[buf][tt+1][cg*8];
                *(float4*)(nk + 4) = *(const float4*)&kb[buf][tt+1][cg*8 + 4];
                *(float4*)(nq)     = *(const float4*)&qb[buf][tt+1][cg*8];
                *(float4*)(nq + 4) = *(const float4*)&qb[buf][tt+1][cg*8 + 4];
                nav  = ab[buf][tt+1][r];
                nbv  = bbuf[buf][tt+1];
                nbvv = nbv * vb[buf][tt+1][r];
            }

            // err partial dot: 2 accumulators, depth 4
            float ea = S[0]*kk[0], eb = S[1]*kk[1];
            ea = fmaf(S[2], kk[2], ea); eb = fmaf(S[3], kk[3], eb);
            ea = fmaf(S[4], kk[4], ea); eb = fmaf(S[5], kk[5], eb);
            ea = fmaf(S[6], kk[6], ea); eb = fmaf(S[7], kk[7], eb);
            float err = ea + eb;
            err += __shfl_xor_sync(0xffffffffu, err, 1);
            err += __shfl_xor_sync(0xffffffffu, err, 2);
            err += __shfl_xor_sync(0xffffffffu, err, 4);

            // aS computed during shfl wait (independent of err)
            float aS[8];
            #pragma unroll
            for (int j = 0; j < 8; j++) aS[j] = av * S[j];

            float ccf = fmaf(bv, err, -bvv);

            float oa = 0.0f, ob = 0.0f;
            #pragma unroll
            for (int j = 0; j < 8; j++) {
                S[j] = fmaf(-ccf, kk[j], aS[j]);
                if (j & 1) ob = fmaf(S[j], qq[j], ob);
                else       oa = fmaf(S[j], qq[j], oa);
            }
            float op = oa + ob;
            op += __shfl_xor_sync(0xffffffffu, op, 1);
            op += __shfl_xor_sync(0xffffffffu, op, 2);
            op += __shfl_xor_sync(0xffffffffu, op, 4);
            if (cg == 0)
                o[(base + (size_t)(c*TCH + tt) * HH) * 64 + i] = op;

            // rotate prefetched registers into current
            #pragma unroll
            for (int j = 0; j < 8; j++) { kk[j] = nk[j]; qq[j] = nq[j]; }
            av = nav; bv = nbv; bvv = nbvv;
        }
        __syncthreads();
    }
}

// =====================================================================
// LayerNorm + gate (zg pre-sigmoided), emits bf16 hi/lo
// =====================================================================
__global__ __launch_bounds__(256) void ln_gate(
    const float* __restrict__ o, const float* __restrict__ zg,
    const float* __restrict__ lnw, const float* __restrict__ lnb,
    __nv_bfloat16* __restrict__ oghi, __nv_bfloat16* __restrict__ oglo)
{
    int warp = (blockIdx.x * blockDim.x + threadIdx.x) >> 5;
    int lane = threadIdx.x & 31;
    if (warp >= MT * HH) return;
    const float* op = o + (size_t)warp * 64;

    float v0 = op[lane], v1 = op[lane + 32];
    float s = v0 + v1;
    #pragma unroll
    for (int m = 16; m >= 1; m >>= 1) s += __shfl_xor_sync(0xffffffffu, s, m);
    float mu = s * (1.0f / 64.0f);
    float d0 = v0 - mu, d1 = v1 - mu;
    float qs = d0*d0 + d1*d1;
    #pragma unroll
    for (int m = 16; m >= 1; m >>= 1) qs += __shfl_xor_sync(0xffffffffu, qs, m);
    float inv = rsqrtf(qs * (1.0f / 64.0f) + LNEPS);

    float y0 = d0 * inv * lnw[lane]      + lnb[lane];
    float y1 = d1 * inv * lnw[lane + 32] + lnb[lane + 32];
    float f0 = y0 * zg[(size_t)warp * 64 + lane];
    float f1 = y1 * zg[(size_t)warp * 64 + lane + 32];

    __nv_bfloat16 h0 = __float2bfloat16(f0);
    __nv_bfloat16 h1 = __float2bfloat16(f1);
    size_t base = (size_t)warp * 64;
    oghi[base + lane]      = h0;
    oghi[base + lane + 32] = h1;
    oglo[base + lane]      = __float2bfloat16(f0 - __bfloat162float(h0));
    oglo[base + lane + 32] = __float2bfloat16(f1 - __bfloat162float(h1));
}

// =====================================================================
// launcher
// =====================================================================
extern "C" void kernel_launch(void* const* d_in, const int* in_sizes, int n_in,
                              void* d_out, int out_size)
{
    const float* x   = (const float*)d_in[0];
    const float* Wq  = (const float*)d_in[1];
    const float* Wk  = (const float*)d_in[2];
    const float* Wv  = (const float*)d_in[3];
    const float* Wa  = (const float*)d_in[4];
    const float* ba  = (const float*)d_in[5];
    const float* Wb  = (const float*)d_in[6];
    const float* bbv = (const float*)d_in[7];
    const float* Wg  = (const float*)d_in[8];
    const float* Wo  = (const float*)d_in[9];
    const float* qcw = (const float*)d_in[10];
    const float* qcb = (const float*)d_in[11];
    const float* kcw = (const float*)d_in[12];
    const float* kcb = (const float*)d_in[13];
    const float* vcw = (const float*)d_in[14];
    const float* vcb = (const float*)d_in[15];
    const float* lnw = (const float*)d_in[16];
    const float* lnb = (const float*)d_in[17];
    float* out = (float*)d_out;

    float *zq, *zk, *zv, *za, *zg, *zb, *qb_, *kb_, *vb_, *ob_;
    __nv_bfloat16 *xhi, *xlo, *whi, *wlo, *oghi, *oglo;
    cudaGetSymbolAddress((void**)&zq,  g_zq);
    cudaGetSymbolAddress((void**)&zk,  g_zk);
    cudaGetSymbolAddress((void**)&zv,  g_zv);
    cudaGetSymbolAddress((void**)&za,  g_za);
    cudaGetSymbolAddress((void**)&zg,  g_zg);
    cudaGetSymbolAddress((void**)&zb,  g_zb);
    cudaGetSymbolAddress((void**)&qb_, g_q);
    cudaGetSymbolAddress((void**)&kb_, g_k);
    cudaGetSymbolAddress((void**)&vb_, g_v);
    cudaGetSymbolAddress((void**)&ob_, g_o);
    cudaGetSymbolAddress((void**)&xhi, g_xhi);
    cudaGetSymbolAddress((void**)&xlo, g_xlo);
    cudaGetSymbolAddress((void**)&whi, g_whi);
    cudaGetSymbolAddress((void**)&wlo, g_wlo);
    cudaGetSymbolAddress((void**)&oghi, g_oghi);
    cudaGetSymbolAddress((void**)&oglo, g_oglo);

    const int GEMM_SMEM = 1024 + NSTAGE * (int)STAGEB;   // 197632
    cudaFuncSetAttribute(gemm_mma5, cudaFuncAttributeMaxDynamicSharedMemorySize, GEMM_SMEM);
    cudaFuncSetAttribute(gemm_mma1, cudaFuncAttributeMaxDynamicSharedMemorySize, GEMM_SMEM);

    // scan at my launch index 3 => profiled by ncu (-s 5, 2 harness pre-launches)
    prep_all<<<dim3(512, 9), 256>>>(x, Wq, Wk, Wv, Wa, Wg, Wo,
                                    whi, wlo, xhi, xlo, Wb, bbv, zb);                   // 0
    gemm_mma5<<<dim3(8 * 5, MT / 128), GTHR, GEMM_SMEM>>>(
        xhi, xlo, whi, wlo, zq, zk, zv, za, zg, ba);                                    // 1
    conv3<<<dim3((MT * 256) / 256, 3), 256>>>(zq, zk, zv, qcw, qcb, kcw, kcb, vcw, vcb,
                                              qb_, kb_, vb_);                           // 2
    scan_kernel<<<dim3(4, HH, BB), 128>>>(qb_, kb_, vb_, za, zb, ob_);                  // 3 (profiled)
    ln_gate<<<(MT * HH * 32) / 256, 256>>>(ob_, zg, lnw, lnb, oghi, oglo);              // 4
    gemm_mma1<<<dim3(HIDD / 128, MT / 128), GTHR, GEMM_SMEM>>>(
        oghi, oglo, whi + 5*(size_t)(HIDD*HIDD), wlo + 5*(size_t)(HIDD*HIDD), out);     // 5
}

// round 15
// speedup vs baseline: 1.6098x; 1.6098x over previous
#include <cuda_runtime.h>
#include <cuda_bf16.h>
#include <math.h>
#include <stdint.h>

// ---------------- problem constants ----------------
#define BB   2
#define TT   2048
#define HIDD 1024
#define HH   16
#define MT   (BB*TT)          // 4096 rows
#define KSCALE 0.125f
#define LNEPS 1e-5f
#define GK   1024             // GEMM K
#define NCHUNK 16             // 1024/64

// ---------------- scratch (device globals) ----------------
__device__ float g_zq[MT*HIDD];
__device__ float g_zk[MT*HIDD];
__device__ float g_zv[MT*HIDD];
__device__ float g_za[MT*HIDD];
__device__ float g_zg[MT*HIDD];
__device__ float g_zb[MT*HH];
__device__ float g_q [MT*HIDD];
__device__ float g_k [MT*HIDD];
__device__ float g_v [MT*HIDD];
__device__ float g_o [MT*HIDD];

__device__ __nv_bfloat16 g_xhi[MT*HIDD];
__device__ __nv_bfloat16 g_xlo[MT*HIDD];
__device__ __nv_bfloat16 g_whi[6*HIDD*HIDD];
__device__ __nv_bfloat16 g_wlo[6*HIDD*HIDD];
__device__ __nv_bfloat16 g_oghi[MT*HIDD];
__device__ __nv_bfloat16 g_oglo[MT*HIDD];

__device__ __forceinline__ float sigmoidf_(float x) {
    return 1.0f / (1.0f + __expf(-x));
}

// ---------------- cp.async helpers ----------------
__device__ __forceinline__ void cp_async16_s(uint32_t dst, const void* src) {
    asm volatile("cp.async.cg.shared.global [%0], [%1], 16;\n" :: "r"(dst), "l"(src));
}
__device__ __forceinline__ void cp_async16(void* dst, const void* src) {
    unsigned d = (unsigned)__cvta_generic_to_shared(dst);
    asm volatile("cp.async.ca.shared.global [%0], [%1], 16;\n" :: "r"(d), "l"(src));
}
__device__ __forceinline__ void cp_async4(void* dst, const void* src) {
    unsigned d = (unsigned)__cvta_generic_to_shared(dst);
    asm volatile("cp.async.ca.shared.global [%0], [%1], 4;\n" :: "r"(d), "l"(src));
}
__device__ __forceinline__ void cp_commit() { asm volatile("cp.async.commit_group;\n"); }
__device__ __forceinline__ void cp_wait2()  { asm volatile("cp.async.wait_group 2;\n"); }
__device__ __forceinline__ void cp_wait1()  { asm volatile("cp.async.wait_group 1;\n"); }
__device__ __forceinline__ void cp_wait0()  { asm volatile("cp.async.wait_group 0;\n"); }

// ---------------- mma.sync / ldmatrix ----------------
__device__ __forceinline__ void ldsm4(uint32_t* r, uint32_t addr) {
    asm volatile("ldmatrix.sync.aligned.m8n8.x4.shared.b16 {%0,%1,%2,%3}, [%4];"
        : "=r"(r[0]), "=r"(r[1]), "=r"(r[2]), "=r"(r[3]) : "r"(addr));
}
__device__ __forceinline__ void mma16816(float* c, const uint32_t* a, const uint32_t* b) {
    asm volatile("mma.sync.aligned.m16n8k16.row.col.f32.bf16.bf16.f32 "
        "{%0,%1,%2,%3}, {%4,%5,%6,%7}, {%8,%9}, {%0,%1,%2,%3};"
        : "+f"(c[0]), "+f"(c[1]), "+f"(c[2]), "+f"(c[3])
        : "r"(a[0]), "r"(a[1]), "r"(a[2]), "r"(a[3]), "r"(b[0]), "r"(b[1]));
}

// =====================================================================
// fp32 -> bf16 hi/lo split, 4x ILP
// =====================================================================
__global__ __launch_bounds__(256) void split_bf16(
    const float* __restrict__ in, __nv_bfloat16* __restrict__ hi,
    __nv_bfloat16* __restrict__ lo, int n4)
{
    int base = blockIdx.x * 1024 + threadIdx.x;
    float4 xv[4];
    #pragma unroll
    for (int j = 0; j < 4; j++) {
        int i = base + j * 256;
        if (i < n4) xv[j] = ((const float4*)in)[i];
    }
    #pragma unroll
    for (int j = 0; j < 4; j++) {
        int i = base + j * 256;
        if (i >= n4) continue;
        float xs[4] = {xv[j].x, xv[j].y, xv[j].z, xv[j].w};
        __align__(8) __nv_bfloat16 h[4];
        __align__(8) __nv_bfloat16 l[4];
        #pragma unroll
        for (int q = 0; q < 4; q++) {
            h[q] = __float2bfloat16(xs[q]);
            l[q] = __float2bfloat16(xs[q] - __bfloat162float(h[q]));
        }
        *(uint2*)(hi + (size_t)i * 4) = *(uint2*)h;
        *(uint2*)(lo + (size_t)i * 4) = *(uint2*)l;
    }
}

// fused 6-weight split, 4x ILP; grid.y selects weight
__global__ __launch_bounds__(256) void split_w6(
    const float* w0, const float* w1, const float* w2,
    const float* w3, const float* w4, const float* w5,
    __nv_bfloat16* __restrict__ hi, __nv_bfloat16* __restrict__ lo)
{
    const int slot = blockIdx.y;
    const float* in = (slot == 0) ? w0 : (slot == 1) ? w1 : (slot == 2) ? w2
                    : (slot == 3) ? w3 : (slot == 4) ? w4 : w5;
    const size_t W = (size_t)HIDD * HIDD;
    int base = blockIdx.x * 1024 + threadIdx.x;
    float4 xv[4];
    #pragma unroll
    for (int j = 0; j < 4; j++)
        xv[j] = ((const float4*)in)[base + j * 256];
    #pragma unroll
    for (int j = 0; j < 4; j++) {
        int i = base + j * 256;
        float xs[4] = {xv[j].x, xv[j].y, xv[j].z, xv[j].w};
        __align__(8) __nv_bfloat16 h[4];
        __align__(8) __nv_bfloat16 l[4];
        #pragma unroll
        for (int q = 0; q < 4; q++) {
            h[q] = __float2bfloat16(xs[q]);
            l[q] = __float2bfloat16(xs[q] - __bfloat162float(h[q]));
        }
        *(uint2*)(hi + slot * W + (size_t)i * 4) = *(uint2*)h;
        *(uint2*)(lo + slot * W + (size_t)i * 4) = *(uint2*)l;
    }
}

// =====================================================================
// bf16x3 GEMM 128x128 tile, K-chunk 64, SW128, 3-stage cp.async pipeline.
// 512 threads = 16 warps (4 M x 4 N), warp tile 32x32.  (R8 config)
// =====================================================================
#define TILEB  16384u
#define STAGEB (4u*TILEB)
#define NSTAGE 3
#define GTHR   512

__device__ __forceinline__ void gemm_core_w(
    const __nv_bfloat16* __restrict__ baseAh, const __nv_bfloat16* __restrict__ baseAl,
    const __nv_bfloat16* __restrict__ baseBh, const __nv_bfloat16* __restrict__ baseBl,
    const float* __restrict__ bias, float* __restrict__ Cbase, int mode)
{
    extern __shared__ char dyns[];
    uint32_t sb0 = (uint32_t)__cvta_generic_to_shared(dyns);
    const uint32_t tiles = (sb0 + 1023) & ~1023u;

    const int tid  = threadIdx.x;
    const int wid  = tid >> 5;
    const int lane = tid & 31;
    const int mbase = (wid >> 2) * 32;
    const int nbase = (wid & 3) * 32;

    const uint32_t sx  = (uint32_t)((lane & 7) << 4);
    const uint32_t khA = (lane & 16) ? 16u : 0u;
    const uint32_t khB = (lane & 8)  ? 16u : 0u;
    uint32_t rowA[2], rowB[2];
    #pragma unroll
    for (int mf = 0; mf < 2; mf++)
        rowA[mf] = (uint32_t)((mbase + mf * 16 + (lane & 15)) * 128);
    #pragma unroll
    for (int nf2 = 0; nf2 < 2; nf2++)
        rowB[nf2] = (uint32_t)((nbase + nf2 * 16 + (lane & 7) + ((lane & 16) ? 8 : 0)) * 128);

    float acc[2][4][4];
    #pragma unroll
    for (int mf = 0; mf < 2; mf++)
        #pragma unroll
        for (int nf = 0; nf < 4; nf++)
            #pragma unroll
            for (int j = 0; j < 4; j++) acc[mf][nf][j] = 0.0f;

    auto issue = [&](int kc, int st) {
        uint32_t tb = tiles + (uint32_t)st * STAGEB;
        #pragma unroll
        for (int it = 0; it < 2; it++) {
            int v = tid + it * GTHR;
            int row = v >> 3, c8 = v & 7;
            uint32_t off = (uint32_t)(row * 128 + c8 * 16);
            uint32_t sw  = off ^ ((off >> 3) & 0x70);
            size_t goff = (size_t)row * GK + (size_t)kc * 64 + c8 * 8;
            cp_async16_s(tb + sw,             baseAh + goff);
            cp_async16_s(tb + TILEB + sw,     baseAl + goff);
            cp_async16_s(tb + 2u*TILEB + sw,  baseBh + goff);
            cp_async16_s(tb + 3u*TILEB + sw,  baseBl + goff);
        }
    };

    issue(0, 0); cp_commit();
    issue(1, 1); cp_commit();
    issue(2, 2); cp_commit();

    for (int c = 0; c < NCHUNK; c++) {
        if (c <= NCHUNK - 3)      cp_wait2();
        else if (c == NCHUNK - 2) cp_wait1();
        else                      cp_wait0();
        __syncthreads();

        const int st = c % NSTAGE;
        const uint32_t tbAh = tiles + (uint32_t)st * STAGEB;
        const uint32_t tbAl = tbAh + TILEB;
        const uint32_t tbBh = tbAl + TILEB;
        const uint32_t tbBl = tbBh + TILEB;

        #pragma unroll
        for (int s = 0; s < 4; s++) {
            const uint32_t kxA = ((uint32_t)(s * 32) + khA) ^ sx;
            const uint32_t kxB = ((uint32_t)(s * 32) + khB) ^ sx;

            uint32_t ah[2][4], al[2][4], bh[4][2], bl[4][2];
            #pragma unroll
            for (int mf = 0; mf < 2; mf++) {
                ldsm4(ah[mf], tbAh + rowA[mf] + kxA);
                ldsm4(al[mf], tbAl + rowA[mf] + kxA);
            }
            #pragma unroll
            for (int nf2 = 0; nf2 < 2; nf2++) {
                uint32_t t[4];
                ldsm4(t, tbBh + rowB[nf2] + kxB);
                bh[nf2*2][0] = t[0]; bh[nf2*2][1] = t[1];
                bh[nf2*2+1][0] = t[2]; bh[nf2*2+1][1] = t[3];
                ldsm4(t, tbBl + rowB[nf2] + kxB);
                bl[nf2*2][0] = t[0]; bl[nf2*2][1] = t[1];
                bl[nf2*2+1][0] = t[2]; bl[nf2*2+1][1] = t[3];
            }
            #pragma unroll
            for (int mf = 0; mf < 2; mf++)
                #pragma unroll
                for (int nf = 0; nf < 4; nf++) {
                    mma16816(acc[mf][nf], ah[mf], bh[nf]);
                    mma16816(acc[mf][nf], ah[mf], bl[nf]);
                    mma16816(acc[mf][nf], al[mf], bh[nf]);
                }
        }
        __syncthreads();

        if (c + NSTAGE < NCHUNK) {
            issue(c + NSTAGE, st);
            cp_commit();
        }
    }

    const int rq = lane >> 2;
    const int cq = (lane & 3) * 2;
    #pragma unroll
    for (int mf = 0; mf < 2; mf++) {
        #pragma unroll
        for (int nf = 0; nf < 4; nf++) {
            int m0  = mbase + mf * 16 + rq;
            int col = nbase + nf * 8 + cq;
            float r0 = acc[mf][nf][0], r1 = acc[mf][nf][1];
            float r2 = acc[mf][nf][2], r3 = acc[mf][nf][3];
            if (mode == 1) {
                float b0 = bias[col], b1 = bias[col + 1];
                r0 = sigmoidf_(r0 + b0); r1 = sigmoidf_(r1 + b1);
                r2 = sigmoidf_(r2 + b0); r3 = sigmoidf_(r3 + b1);
            } else if (mode == 2) {
                r0 = sigmoidf_(r0); r1 = sigmoidf_(r1);
                r2 = sigmoidf_(r2); r3 = sigmoidf_(r3);
            }
            *(float2*)&Cbase[(size_t)m0 * HIDD + col]       = make_float2(r0, r1);
            *(float2*)&Cbase[(size_t)(m0 + 8) * HIDD + col] = make_float2(r2, r3);
        }
    }
}

__global__ __launch_bounds__(GTHR, 1) void gemm_mma5(
    const __nv_bfloat16* __restrict__ xhi, const __nv_bfloat16* __restrict__ xlo,
    const __nv_bfloat16* __restrict__ whi, const __nv_bfloat16* __restrict__ wlo,
    float* z0, float* z1, float* z2, float* z3, float* z4,
    const float* __restrict__ ba)
{
    const int slot = blockIdx.x >> 3;
    const int bnw  = (blockIdx.x & 7) * 128;
    const int bm   = blockIdx.y * 128;
    const size_t W = (size_t)HIDD * HIDD;
    float* C = (slot == 0) ? z0 : (slot == 1) ? z1 : (slot == 2) ? z2
             : (slot == 3) ? z3 : z4;
    const int mode = (slot == 3) ? 1 : (slot == 4) ? 2 : 0;
    gemm_core_w(xhi + (size_t)bm * GK, xlo + (size_t)bm * GK,
                whi + slot * W + (size_t)bnw * GK, wlo + slot * W + (size_t)bnw * GK,
                (slot == 3) ? (ba + bnw) : nullptr,
                C + (size_t)bm * HIDD + bnw, mode);
}

__global__ __launch_bounds__(GTHR, 1) void gemm_mma1(
    const __nv_bfloat16* __restrict__ Ahi, const __nv_bfloat16* __restrict__ Alo,
    const __nv_bfloat16* __restrict__ Bhi, const __nv_bfloat16* __restrict__ Blo,
    float* __restrict__ C)
{
    const int bn = blockIdx.x * 128;
    const int bm = blockIdx.y * 128;
    gemm_core_w(Ahi + (size_t)bm * GK, Alo + (size_t)bm * GK,
                Bhi + (size_t)bn * GK, Blo + (size_t)bn * GK,
                nullptr, C + (size_t)bm * HIDD + bn, 0);
}

// =====================================================================
// beta GEMV: warp-per-row. grid = MT/8, block = 256 (8 warps).
// =====================================================================
__global__ __launch_bounds__(256) void gemv_beta(
    const float* __restrict__ x, const float* __restrict__ Wb,
    const float* __restrict__ bb, float* __restrict__ zb)
{
    const int tid  = threadIdx.x;
    const int w    = tid >> 5;
    const int lane = tid & 31;
    const int n    = lane >> 1;
    const int kseg = lane & 1;
    const int m    = blockIdx.x * 8 + w;

    const float4* xr = (const float4*)(x  + (size_t)m * HIDD + kseg * 512);
    const float4* wr = (const float4*)(Wb + (size_t)n * HIDD + kseg * 512);

    float a0 = 0.f, a1 = 0.f, a2 = 0.f, a3 = 0.f;
    #pragma unroll 8
    for (int i = 0; i < 128; i += 4) {
        float4 x0 = xr[i+0], w0 = wr[i+0];
        float4 x1 = xr[i+1], w1 = wr[i+1];
        float4 x2 = xr[i+2], w2 = wr[i+2];
        float4 x3 = xr[i+3], w3 = wr[i+3];
        a0 = fmaf(x0.x, w0.x, a0); a0 = fmaf(x0.y, w0.y, a0);
        a0 = fmaf(x0.z, w0.z, a0); a0 = fmaf(x0.w, w0.w, a0);
        a1 = fmaf(x1.x, w1.x, a1); a1 = fmaf(x1.y, w1.y, a1);
        a1 = fmaf(x1.z, w1.z, a1); a1 = fmaf(x1.w, w1.w, a1);
        a2 = fmaf(x2.x, w2.x, a2); a2 = fmaf(x2.y, w2.y, a2);
        a2 = fmaf(x2.z, w2.z, a2); a2 = fmaf(x2.w, w2.w, a2);
        a3 = fmaf(x3.x, w3.x, a3); a3 = fmaf(x3.y, w3.y, a3);
        a3 = fmaf(x3.z, w3.z, a3); a3 = fmaf(x3.w, w3.w, a3);
    }
    float acc = (a0 + a1) + (a2 + a3);
    acc += __shfl_xor_sync(0xffffffffu, acc, 1);
    if (kseg == 0)
        zb[(size_t)m * HH + n] = sigmoidf_(acc + bb[n]);
}

// =====================================================================
// fused causal depthwise conv (K=4) + SiLU for q/k/v; grid.y selects branch
// =====================================================================
__global__ __launch_bounds__(256) void conv3(
    const float* __restrict__ zq, const float* __restrict__ zk, const float* __restrict__ zv,
    const float* __restrict__ qcw, const float* __restrict__ qcb,
    const float* __restrict__ kcw, const float* __restrict__ kcb,
    const float* __restrict__ vcw, const float* __restrict__ vcb,
    float* __restrict__ oq, float* __restrict__ ok, float* __restrict__ ov)
{
    const int br = blockIdx.y;
    const float* z    = (br == 0) ? zq  : (br == 1) ? zk  : zv;
    const float* w    = (br == 0) ? qcw : (br == 1) ? kcw : vcw;
    const float* bias = (br == 0) ? qcb : (br == 1) ? kcb : vcb;
    float* out        = (br == 0) ? oq  : (br == 1) ? ok  : ov;
    const float scale = (br == 1) ? KSCALE : 1.0f;

    int idx = blockIdx.x * blockDim.x + threadIdx.x;
    int bt = idx >> 8;
    int c0 = (idx & 255) * 4;
    int b  = bt >> 11;
    int t  = bt & 2047;

    float wl[16];
    *(float4*)(wl)      = *(const float4*)&w[c0*4];
    *(float4*)(wl + 4)  = *(const float4*)&w[c0*4 + 4];
    *(float4*)(wl + 8)  = *(const float4*)&w[c0*4 + 8];
    *(float4*)(wl + 12) = *(const float4*)&w[c0*4 + 12];

    float av[4];
    *(float4*)av = *(const float4*)&bias[c0];

    #pragma unroll
    for (int j = 0; j < 4; j++) {
        int tt = t - 3 + j;
        if (tt < 0) continue;
        float zl[4];
        *(float4*)zl = *(const float4*)&z[((size_t)(b*TT + tt)) * HIDD + c0];
        #pragma unroll
        for (int cc = 0; cc < 4; cc++)
            av[cc] = fmaf(wl[cc*4 + j], zl[cc], av[cc]);
    }
    float4 o4;
    float* op = &o4.x;
    #pragma unroll
    for (int cc = 0; cc < 4; cc++) {
        float xv = av[cc];
        op[cc] = scale * xv * sigmoidf_(xv);
    }
    *(float4*)&out[(size_t)bt * HIDD + c0] = o4;
}

// =====================================================================
// Sequential scan (R11): grid (4,H,B) x 128 thr, TCH=16 double-buffered,
// per-chunk scalars hoisted to registers, aS overlap with shfl chain.
// =====================================================================
#define TCH 16
__global__ __launch_bounds__(128) void scan_kernel(
    const float* __restrict__ q, const float* __restrict__ k,
    const float* __restrict__ v, const float* __restrict__ za,
    const float* __restrict__ zb, float* __restrict__ o)
{
    const int rc  = blockIdx.x;
    const int h   = blockIdx.y;
    const int b   = blockIdx.z;
    const int tid = threadIdx.x;
    const int r   = tid >> 3;
    const int cg  = tid & 7;
    const int i   = rc * 16 + r;

    __shared__ __align__(16) float kb[2][TCH][64];
    __shared__ __align__(16) float qb[2][TCH][64];
    __shared__ __align__(16) float vb[2][TCH][16];
    __shared__ __align__(16) float ab[2][TCH][16];
    __shared__ __align__(16) float bbuf[2][TCH];

    float S[8];
    #pragma unroll
    for (int j = 0; j < 8; j++) S[j] = 0.0f;

    const size_t base = ((size_t)b * TT) * HH + h;

    auto issue = [&](int c, int buf) {
        int t0 = c * TCH;
        #pragma unroll
        for (int it = 0; it < 2; it++) {
            int idx = tid + it * 128;
            int tt = idx >> 4, f = idx & 15;
            size_t off = (base + (size_t)(t0 + tt) * HH) * 64 + f * 4;
            cp_async16(&kb[buf][tt][f*4], k + off);
            cp_async16(&qb[buf][tt][f*4], q + off);
        }
        if (tid < 64) {
            int tt = tid >> 2, f = tid & 3;
            size_t off = (base + (size_t)(t0 + tt) * HH) * 64 + rc*16 + f*4;
            cp_async16(&vb[buf][tt][f*4], v + off);
        } else {
            int t2 = tid - 64;
            int tt = t2 >> 2, f = t2 & 3;
            size_t off = (base + (size_t)(t0 + tt) * HH) * 64 + rc*16 + f*4;
            cp_async16(&ab[buf][tt][f*4], za + off);
        }
        if (tid < TCH)
            cp_async4(&bbuf[buf][tid], zb + ((size_t)(b*TT + t0 + tid)) * HH + h);
    };

    const int NCH = TT / TCH;
    issue(0, 0);
    cp_commit();

    for (int c = 0; c < NCH; c++) {
        const int buf = c & 1;
        if (c + 1 < NCH) {
            issue(c + 1, buf ^ 1);
            cp_commit();
            cp_wait1();
        } else {
            cp_wait0();
        }
        __syncthreads();

        // hoist per-step scalars into registers (off-chain, MLP-overlapped)
        float aa[TCH], bbv[TCH], bvv[TCH];
        #pragma unroll
        for (int tt = 0; tt < TCH; tt++) {
            float bv = bbuf[buf][tt];
            float vv = vb[buf][tt][r];
            aa[tt]  = ab[buf][tt][r];
            bbv[tt] = bv;
            bvv[tt] = bv * vv;
        }

        #pragma unroll
        for (int tt = 0; tt < TCH; tt++) {
            float kk[8], qq[8];
            *(float4*)(kk)     = *(const float4*)&kb[buf][tt][cg*8];
            *(float4*)(kk + 4) = *(const float4*)&kb[buf][tt][cg*8 + 4];
            *(float4*)(qq)     = *(const float4*)&qb[buf][tt][cg*8];
            *(float4*)(qq + 4) = *(const float4*)&qb[buf][tt][cg*8 + 4];

            float ea = S[0]*kk[0], eb = S[1]*kk[1];
            ea = fmaf(S[2], kk[2], ea); eb = fmaf(S[3], kk[3], eb);
            ea = fmaf(S[4], kk[4], ea); eb = fmaf(S[5], kk[5], eb);
            ea = fmaf(S[6], kk[6], ea); eb = fmaf(S[7], kk[7], eb);
            float err = ea + eb;
            err += __shfl_xor_sync(0xffffffffu, err, 1);
            err += __shfl_xor_sync(0xffffffffu, err, 2);
            err += __shfl_xor_sync(0xffffffffu, err, 4);

            float aS[8];
            #pragma unroll
            for (int j = 0; j < 8; j++) aS[j] = aa[tt] * S[j];

            float ccf = fmaf(bbv[tt], err, -bvv[tt]);

            float oa = 0.0f, ob = 0.0f;
            #pragma unroll
            for (int j = 0; j < 8; j++) {
                S[j] = fmaf(-ccf, kk[j], aS[j]);
                if (j & 1) ob = fmaf(S[j], qq[j], ob);
                else       oa = fmaf(S[j], qq[j], oa);
            }
            float op = oa + ob;
            op += __shfl_xor_sync(0xffffffffu, op, 1);
            op += __shfl_xor_sync(0xffffffffu, op, 2);
            op += __shfl_xor_sync(0xffffffffu, op, 4);
            if (cg == 0)
                o[(base + (size_t)(c*TCH + tt) * HH) * 64 + i] = op;
        }
        __syncthreads();
    }
}

// =====================================================================
// LayerNorm + gate (zg pre-sigmoided), emits bf16 hi/lo
// =====================================================================
__global__ __launch_bounds__(256) void ln_gate(
    const float* __restrict__ o, const float* __restrict__ zg,
    const float* __restrict__ lnw, const float* __restrict__ lnb,
    __nv_bfloat16* __restrict__ oghi, __nv_bfloat16* __restrict__ oglo)
{
    int warp = (blockIdx.x * blockDim.x + threadIdx.x) >> 5;
    int lane = threadIdx.x & 31;
    if (warp >= MT * HH) return;
    const float* op = o + (size_t)warp * 64;

    float v0 = op[lane], v1 = op[lane + 32];
    float s = v0 + v1;
    #pragma unroll
    for (int m = 16; m >= 1; m >>= 1) s += __shfl_xor_sync(0xffffffffu, s, m);
    float mu = s * (1.0f / 64.0f);
    float d0 = v0 - mu, d1 = v1 - mu;
    float qs = d0*d0 + d1*d1;
    #pragma unroll
    for (int m = 16; m >= 1; m >>= 1) qs += __shfl_xor_sync(0xffffffffu, qs, m);
    float inv = rsqrtf(qs * (1.0f / 64.0f) + LNEPS);

    float y0 = d0 * inv * lnw[lane]      + lnb[lane];
    float y1 = d1 * inv * lnw[lane + 32] + lnb[lane + 32];
    float f0 = y0 * zg[(size_t)warp * 64 + lane];
    float f1 = y1 * zg[(size_t)warp * 64 + lane + 32];

    __nv_bfloat16 h0 = __float2bfloat16(f0);
    __nv_bfloat16 h1 = __float2bfloat16(f1);
    size_t base = (size_t)warp * 64;
    oghi[base + lane]      = h0;
    oghi[base + lane + 32] = h1;
    oglo[base + lane]      = __float2bfloat16(f0 - __bfloat162float(h0));
    oglo[base + lane + 32] = __float2bfloat16(f1 - __bfloat162float(h1));
}

// =====================================================================
// launcher
// =====================================================================
extern "C" void kernel_launch(void* const* d_in, const int* in_sizes, int n_in,
                              void* d_out, int out_size)
{
    const float* x   = (const float*)d_in[0];
    const float* Wq  = (const float*)d_in[1];
    const float* Wk  = (const float*)d_in[2];
    const float* Wv  = (const float*)d_in[3];
    const float* Wa  = (const float*)d_in[4];
    const float* ba  = (const float*)d_in[5];
    const float* Wb  = (const float*)d_in[6];
    const float* bbv = (const float*)d_in[7];
    const float* Wg  = (const float*)d_in[8];
    const float* Wo  = (const float*)d_in[9];
    const float* qcw = (const float*)d_in[10];
    const float* qcb = (const float*)d_in[11];
    const float* kcw = (const float*)d_in[12];
    const float* kcb = (const float*)d_in[13];
    const float* vcw = (const float*)d_in[14];
    const float* vcb = (const float*)d_in[15];
    const float* lnw = (const float*)d_in[16];
    const float* lnb = (const float*)d_in[17];
    float* out = (float*)d_out;

    float *zq, *zk, *zv, *za, *zg, *zb, *qb_, *kb_, *vb_, *ob_;
    __nv_bfloat16 *xhi, *xlo, *whi, *wlo, *oghi, *oglo;
    cudaGetSymbolAddress((void**)&zq,  g_zq);
    cudaGetSymbolAddress((void**)&zk,  g_zk);
    cudaGetSymbolAddress((void**)&zv,  g_zv);
    cudaGetSymbolAddress((void**)&za,  g_za);
    cudaGetSymbolAddress((void**)&zg,  g_zg);
    cudaGetSymbolAddress((void**)&zb,  g_zb);
    cudaGetSymbolAddress((void**)&qb_, g_q);
    cudaGetSymbolAddress((void**)&kb_, g_k);
    cudaGetSymbolAddress((void**)&vb_, g_v);
    cudaGetSymbolAddress((void**)&ob_, g_o);
    cudaGetSymbolAddress((void**)&xhi, g_xhi);
    cudaGetSymbolAddress((void**)&xlo, g_xlo);
    cudaGetSymbolAddress((void**)&whi, g_whi);
    cudaGetSymbolAddress((void**)&wlo, g_wlo);
    cudaGetSymbolAddress((void**)&oghi, g_oghi);
    cudaGetSymbolAddress((void**)&oglo, g_oglo);

    const int GEMM_SMEM = 1024 + NSTAGE * (int)STAGEB;   // 197632
    cudaFuncSetAttribute(gemm_mma5, cudaFuncAttributeMaxDynamicSharedMemorySize, GEMM_SMEM);
    cudaFuncSetAttribute(gemm_mma1, cudaFuncAttributeMaxDynamicSharedMemorySize, GEMM_SMEM);

    const int W4 = HIDD * HIDD / 4;
    const int X4 = MT * HIDD / 4;

    // R8 launch structure (best known: 809us) + R11 scan
    split_bf16<<<(X4/2) / 1024, 256>>>(x, xhi, xlo, X4/2);                              // 0
    split_bf16<<<(X4/2) / 1024, 256>>>(x + (size_t)X4/2*4,
                                      xhi + (size_t)X4/2*4, xlo + (size_t)X4/2*4, X4/2); // 1
    split_w6<<<dim3(W4 / 1024, 6), 256>>>(Wq, Wk, Wv, Wa, Wg, Wo, whi, wlo);            // 2
    gemm_mma5<<<dim3(8 * 5, MT / 128), GTHR, GEMM_SMEM>>>(
        xhi, xlo, whi, wlo, zq, zk, zv, za, zg, ba);                                    // 3 (profiled)
    gemv_beta<<<MT / 8, 256>>>(x, Wb, bbv, zb);                                         // 4
    conv3<<<dim3((MT * 256) / 256, 3), 256>>>(zq, zk, zv, qcw, qcb, kcw, kcb, vcw, vcb,
                                              qb_, kb_, vb_);                           // 5
    scan_kernel<<<dim3(4, HH, BB), 128>>>(qb_, kb_, vb_, za, zb, ob_);                  // 6
    ln_gate<<<(MT * HH * 32) / 256, 256>>>(ob_, zg, lnw, lnb, oghi, oglo);              // 7
    gemm_mma1<<<dim3(HIDD / 128, MT / 128), GTHR, GEMM_SMEM>>>(
        oghi, oglo, whi + 5*(size_t)(HIDD*HIDD), wlo + 5*(size_t)(HIDD*HIDD), out);     // 8
}